// round 13
// baseline (speedup 1.0000x reference)
#include <cuda_runtime.h>
#include <cuda_fp16.h>
#include <math.h>
#include <stdint.h>

#define Vv 32000
#define Hh 512
#define Bb 128
#define Ss 64

#define WH_SPLIT 8
#define G_SPLIT  16

// ---- scratch ----
// P_wh[8][B*H] | rnn3[B*3H] | P_g[16][B*4H] | scores[B*S]
#define OFF_WH   0
#define OFF_RNN  (WH_SPLIT*Bb*Hh)
#define OFF_GATE (OFF_RNN + Bb*3*Hh)
#define OFF_SC   (OFF_GATE + G_SPLIT*Bb*4*Hh)
#define SCRATCH_TOTAL (OFF_SC + Bb*Ss)
__device__ float g_scratch[SCRATCH_TOTAL];

__device__ __forceinline__ float sigmoidf_(float x) {
    return 1.0f / (1.0f + __expf(-x));
}
__device__ __forceinline__ float tanh_fast(float x) {
    float y; asm("tanh.approx.f32 %0, %1;" : "=f"(y) : "f"(x)); return y;
}
__device__ __forceinline__ uint32_t pack_h2(float lo, float hi) {
    uint32_t r;
    asm("cvt.rn.f16x2.f32 %0, %1, %2;" : "=r"(r) : "f"(hi), "f"(lo));
    return r;
}
__device__ __forceinline__ void mma_f16(float c[4],
    uint32_t a0, uint32_t a1, uint32_t a2, uint32_t a3,
    uint32_t b0, uint32_t b1)
{
    asm volatile(
        "mma.sync.aligned.m16n8k16.row.col.f32.f16.f16.f32 "
        "{%0,%1,%2,%3}, {%4,%5,%6,%7}, {%8,%9}, {%0,%1,%2,%3};"
        : "+f"(c[0]), "+f"(c[1]), "+f"(c[2]), "+f"(c[3])
        : "r"(a0), "r"(a1), "r"(a2), "r"(a3), "r"(b0), "r"(b1));
}
__device__ __forceinline__ void ldsm_x4(uint32_t& r0, uint32_t& r1,
                                        uint32_t& r2, uint32_t& r3,
                                        uint32_t saddr)
{
    asm volatile("ldmatrix.sync.aligned.m8n8.x4.shared.b16 {%0,%1,%2,%3}, [%4];"
                 : "=r"(r0), "=r"(r1), "=r"(r2), "=r"(r3) : "r"(saddr));
}

#define SSTH 40
#define HBUF (128*SSTH)
#define MMA3H_SMEM (4*HBUF*2)

// ============================================================
// BN=128 fp16 GEMM (R7 skeleton) + fused score epilogue option.
// (used for Wh split-K and the fused We+score GEMM)
// ============================================================
template<bool BIAS, bool SCORE, bool ZEROSC>
__global__ __launch_bounds__(256)
void mma3h(const float* __restrict__ A, int lda,
           const float* __restrict__ B0, int ldb0,
           const float* __restrict__ B1, int ldb1, int Kswitch,
           float* __restrict__ C, int ldc, int cslice,
           const float* __restrict__ bias, int Kslice,
           const float* __restrict__ Pwh,
           const float* __restrict__ vvec,
           float* __restrict__ scores)
{
    extern __shared__ __half shh[];

    const int m0 = blockIdx.y * 128;
    const int n0 = blockIdx.x * 128;
    const int kbase = blockIdx.z * Kslice;
    if (!SCORE) C += (size_t)blockIdx.z * cslice;

    const int t    = threadIdx.x;
    const int lane = t & 31;
    const int warp = t >> 5;
    const int wm = warp & 1;
    const int wn = warp >> 1;
    const int g  = lane >> 2;
    const int tg = lane & 3;

    if (ZEROSC) {
        int id = (blockIdx.z * gridDim.x + blockIdx.x) * 256 + t;
        scores[id] = 0.0f;
    }

    const uint32_t as_base = (uint32_t)__cvta_generic_to_shared(shh);
    const uint32_t bs_base = as_base + 2u * HBUF * 2u;
    const uint32_t a_loff = (uint32_t)(((lane & 15) * SSTH + ((lane >> 4) << 3)) * 2);
    const uint32_t b_loff = (uint32_t)((((lane & 7) + ((lane >> 4) << 3)) * SSTH
                                        + (((lane >> 3) & 1) << 3)) * 2);

    const int lrow = t >> 3;
    const int lcol = (t & 7) * 4;

    float4 abuf[4], bbuf[4];

    auto ldg_stage = [&](int kc) {
        #pragma unroll
        for (int i = 0; i < 4; i++) {
            int r = lrow + 32 * i;
            int kabs = kbase + kc + lcol;
            abuf[i] = *(const float4*)&A[(size_t)(m0 + r) * lda + kabs];
            const float* bp = (kabs < Kswitch)
                ? (B0 + (size_t)(n0 + r) * ldb0 + kabs)
                : (B1 + (size_t)(n0 + r) * ldb1 + (kabs - Kswitch));
            bbuf[i] = *(const float4*)bp;
        }
    };
    auto sts_stage = [&](int s) {
        __half* As = shh + (size_t)s * HBUF;
        __half* Bs = shh + 2 * HBUF + (size_t)s * HBUF;
        #pragma unroll
        for (int i = 0; i < 4; i++) {
            int r = lrow + 32 * i;
            uint2 ua = make_uint2(pack_h2(abuf[i].x, abuf[i].y),
                                  pack_h2(abuf[i].z, abuf[i].w));
            *(uint2*)&As[r * SSTH + lcol] = ua;
            uint2 ub = make_uint2(pack_h2(bbuf[i].x, bbuf[i].y),
                                  pack_h2(bbuf[i].z, bbuf[i].w));
            *(uint2*)&Bs[r * SSTH + lcol] = ub;
        }
    };

    float acc[4][4][4];
    #pragma unroll
    for (int mi = 0; mi < 4; mi++)
        #pragma unroll
        for (int ni = 0; ni < 4; ni++)
            #pragma unroll
            for (int k = 0; k < 4; k++) acc[mi][ni][k] = 0.0f;

    const int nk = Kslice >> 5;

    ldg_stage(0);
    sts_stage(0);
    if (nk > 1) ldg_stage(32);
    __syncthreads();

    for (int kt = 0; kt < nk; kt++) {
        const int cur = kt & 1;
        const uint32_t abufp = as_base + (uint32_t)cur * (HBUF * 2u);
        const uint32_t bbufp = bs_base + (uint32_t)cur * (HBUF * 2u);

        #pragma unroll
        for (int kk = 0; kk < 32; kk += 16) {
            uint32_t af[4][4], bf[4][2];
            #pragma unroll
            for (int mi = 0; mi < 4; mi++) {
                uint32_t addr = abufp
                    + (uint32_t)(((wm * 64 + mi * 16) * SSTH + kk) * 2) + a_loff;
                ldsm_x4(af[mi][0], af[mi][1], af[mi][2], af[mi][3], addr);
            }
            #pragma unroll
            for (int p = 0; p < 2; p++) {
                uint32_t addr = bbufp
                    + (uint32_t)(((wn * 32 + p * 16) * SSTH + kk) * 2) + b_loff;
                ldsm_x4(bf[2*p][0], bf[2*p][1], bf[2*p+1][0], bf[2*p+1][1], addr);
            }
            #pragma unroll
            for (int mi = 0; mi < 4; mi++)
                #pragma unroll
                for (int ni = 0; ni < 4; ni++)
                    mma_f16(acc[mi][ni],
                            af[mi][0], af[mi][1], af[mi][2], af[mi][3],
                            bf[ni][0], bf[ni][1]);
        }

        if (kt + 1 < nk) {
            sts_stage(cur ^ 1);
            __syncthreads();
            if (kt + 2 < nk) ldg_stage((kt + 2) << 5);
        }
    }

    if (SCORE) {
        float* sW = (float*)shh;           // [2][128]
        float* sv = sW + 256;              // [128]
        __syncthreads();
        {
            const int b0 = m0 >> 6;
            const int bi = t >> 7;
            const int nn = t & 127;
            float w = bias[n0 + nn];       // attn_b
            #pragma unroll
            for (int z = 0; z < WH_SPLIT; z++)
                w += Pwh[(size_t)z * Bb * Hh + (size_t)(b0 + bi) * Hh + n0 + nn];
            sW[bi * 128 + nn] = w;
            if (t < 128) sv[t] = vvec[n0 + t];
        }
        __syncthreads();

        #pragma unroll
        for (int mi = 0; mi < 4; mi++) {
            #pragma unroll
            for (int ci = 0; ci < 2; ci++) {
                int r  = wm * 64 + mi * 16 + g + ci * 8;
                int rb = r >> 6;
                float part = 0.0f;
                #pragma unroll
                for (int ni = 0; ni < 4; ni++) {
                    int nl = wn * 32 + ni * 8 + tg * 2;
                    part += sv[nl]     * tanh_fast(acc[mi][ni][ci*2+0] + sW[rb*128 + nl]);
                    part += sv[nl + 1] * tanh_fast(acc[mi][ni][ci*2+1] + sW[rb*128 + nl + 1]);
                }
                part += __shfl_xor_sync(0xFFFFFFFFu, part, 1);
                part += __shfl_xor_sync(0xFFFFFFFFu, part, 2);
                if (tg == 0)
                    atomicAdd(&scores[m0 + r], part);
            }
        }
        return;
    }

    #pragma unroll
    for (int mi = 0; mi < 4; mi++) {
        #pragma unroll
        for (int ci = 0; ci < 2; ci++) {
            int m = m0 + wm * 64 + mi * 16 + g + ci * 8;
            #pragma unroll
            for (int ni = 0; ni < 4; ni++) {
                int n = n0 + wn * 32 + ni * 8 + tg * 2;
                float2 vo;
                vo.x = acc[mi][ni][ci * 2 + 0];
                vo.y = acc[mi][ni][ci * 2 + 1];
                if (BIAS) { vo.x += bias[n]; vo.y += bias[n + 1]; }
                *(float2*)&C[(size_t)m * ldc + n] = vo;
            }
        }
    }
}

// ============================================================
// BN=64 fp16 GEMM — higher occupancy (3 CTAs/SM) for the
// DRAM-concurrency-bound weight GEMMs (fc, gates).
// BM=128, BN=64, BK=32; warps 4(m) x 2(n); warp tile 32x32.
// smem = A 2x10240 + B 2x5120 = 30720 B (no attribute needed).
// ============================================================
#define HBUF64 (64*SSTH)
#define MMA64_SMEM (2*HBUF*2 + 2*HBUF64*2)   // 30720

template<bool BIAS>
__global__ __launch_bounds__(256)
void mma64(const float* __restrict__ A, int lda,
           const float* __restrict__ B0, int ldb0,
           const float* __restrict__ B1, int ldb1, int Kswitch,
           float* __restrict__ C, int ldc, int cslice,
           const float* __restrict__ bias, int Kslice)
{
    extern __shared__ __half shh[];

    const int m0 = blockIdx.y * 128;
    const int n0 = blockIdx.x * 64;
    const int kbase = blockIdx.z * Kslice;
    C += (size_t)blockIdx.z * cslice;

    const int t    = threadIdx.x;
    const int lane = t & 31;
    const int warp = t >> 5;
    const int wm = warp & 3;       // 0..3 (32 rows each)
    const int wn = warp >> 2;      // 0..1 (32 cols each)
    const int g  = lane >> 2;
    const int tg = lane & 3;

    const uint32_t as_base = (uint32_t)__cvta_generic_to_shared(shh);
    const uint32_t bs_base = as_base + 2u * HBUF * 2u;
    const uint32_t a_loff = (uint32_t)(((lane & 15) * SSTH + ((lane >> 4) << 3)) * 2);
    const uint32_t b_loff = (uint32_t)((((lane & 7) + ((lane >> 4) << 3)) * SSTH
                                        + (((lane >> 3) & 1) << 3)) * 2);

    const int lrow = t >> 3;          // 0..31
    const int lcol = (t & 7) * 4;

    float4 abuf[4], bbuf[2];

    auto ldg_stage = [&](int kc) {
        int kabs = kbase + kc + lcol;
        #pragma unroll
        for (int i = 0; i < 4; i++) {
            int r = lrow + 32 * i;
            abuf[i] = *(const float4*)&A[(size_t)(m0 + r) * lda + kabs];
        }
        #pragma unroll
        for (int i = 0; i < 2; i++) {
            int r = lrow + 32 * i;
            const float* bp = (kabs < Kswitch)
                ? (B0 + (size_t)(n0 + r) * ldb0 + kabs)
                : (B1 + (size_t)(n0 + r) * ldb1 + (kabs - Kswitch));
            bbuf[i] = *(const float4*)bp;
        }
    };
    auto sts_stage = [&](int s) {
        __half* As = shh + (size_t)s * HBUF;
        __half* Bs = shh + 2 * HBUF + (size_t)s * HBUF64;
        #pragma unroll
        for (int i = 0; i < 4; i++) {
            int r = lrow + 32 * i;
            *(uint2*)&As[r * SSTH + lcol] =
                make_uint2(pack_h2(abuf[i].x, abuf[i].y),
                           pack_h2(abuf[i].z, abuf[i].w));
        }
        #pragma unroll
        for (int i = 0; i < 2; i++) {
            int r = lrow + 32 * i;
            *(uint2*)&Bs[r * SSTH + lcol] =
                make_uint2(pack_h2(bbuf[i].x, bbuf[i].y),
                           pack_h2(bbuf[i].z, bbuf[i].w));
        }
    };

    float acc[2][4][4];
    #pragma unroll
    for (int mi = 0; mi < 2; mi++)
        #pragma unroll
        for (int ni = 0; ni < 4; ni++)
            #pragma unroll
            for (int k = 0; k < 4; k++) acc[mi][ni][k] = 0.0f;

    const int nk = Kslice >> 5;

    ldg_stage(0);
    sts_stage(0);
    if (nk > 1) ldg_stage(32);
    __syncthreads();

    for (int kt = 0; kt < nk; kt++) {
        const int cur = kt & 1;
        const uint32_t abufp = as_base + (uint32_t)cur * (HBUF * 2u);
        const uint32_t bbufp = bs_base + (uint32_t)cur * (HBUF64 * 2u);

        #pragma unroll
        for (int kk = 0; kk < 32; kk += 16) {
            uint32_t af[2][4], bf[4][2];
            #pragma unroll
            for (int mi = 0; mi < 2; mi++) {
                uint32_t addr = abufp
                    + (uint32_t)(((wm * 32 + mi * 16) * SSTH + kk) * 2) + a_loff;
                ldsm_x4(af[mi][0], af[mi][1], af[mi][2], af[mi][3], addr);
            }
            #pragma unroll
            for (int p = 0; p < 2; p++) {
                uint32_t addr = bbufp
                    + (uint32_t)(((wn * 32 + p * 16) * SSTH + kk) * 2) + b_loff;
                ldsm_x4(bf[2*p][0], bf[2*p][1], bf[2*p+1][0], bf[2*p+1][1], addr);
            }
            #pragma unroll
            for (int mi = 0; mi < 2; mi++)
                #pragma unroll
                for (int ni = 0; ni < 4; ni++)
                    mma_f16(acc[mi][ni],
                            af[mi][0], af[mi][1], af[mi][2], af[mi][3],
                            bf[ni][0], bf[ni][1]);
        }

        if (kt + 1 < nk) {
            sts_stage(cur ^ 1);
            __syncthreads();
            if (kt + 2 < nk) ldg_stage((kt + 2) << 5);
        }
    }

    #pragma unroll
    for (int mi = 0; mi < 2; mi++) {
        #pragma unroll
        for (int ci = 0; ci < 2; ci++) {
            int m = m0 + wm * 32 + mi * 16 + g + ci * 8;
            #pragma unroll
            for (int ni = 0; ni < 4; ni++) {
                int n = n0 + wn * 32 + ni * 8 + tg * 2;
                float2 vo;
                vo.x = acc[mi][ni][ci * 2 + 0];
                vo.y = acc[mi][ni][ci * 2 + 1];
                if (BIAS) { vo.x += bias[n]; vo.y += bias[n + 1]; }
                *(float2*)&C[(size_t)m * ldc + n] = vo;
            }
        }
    }
}

// ============================================================
// attn tail: embed + h0 copy + softmax(scores) + context
// ============================================================
__global__ __launch_bounds__(512)
void attn_fused(const int* __restrict__ input_ids,
                const float* __restrict__ emb,
                const float* __restrict__ h0,
                const float* __restrict__ enc)
{
    const int b = blockIdx.x;
    const int t = threadIdx.x;
    const int lane = t & 31, warp = t >> 5;

    __shared__ float swgt[Ss];

    {
        int idx = input_ids[b];
        float* rnn3 = g_scratch + OFF_RNN + (size_t)b * (3*Hh);
        rnn3[t]        = emb[(size_t)idx * Hh + t];
        rnn3[2*Hh + t] = h0[(size_t)b * Hh + t];
    }

    if (warp == 0) {
        float x0 = g_scratch[OFF_SC + (size_t)b * Ss + lane];
        float x1 = g_scratch[OFF_SC + (size_t)b * Ss + lane + 32];
        float mx = fmaxf(x0, x1);
        #pragma unroll
        for (int off = 16; off > 0; off >>= 1)
            mx = fmaxf(mx, __shfl_xor_sync(0xFFFFFFFFu, mx, off));
        float e0 = expf(x0 - mx), e1 = expf(x1 - mx);
        float sum = e0 + e1;
        #pragma unroll
        for (int off = 16; off > 0; off >>= 1)
            sum += __shfl_xor_sync(0xFFFFFFFFu, sum, off);
        float inv = 1.0f / sum;
        swgt[lane]      = e0 * inv;
        swgt[lane + 32] = e1 * inv;
    }
    __syncthreads();

    {
        const float* encb = enc + (size_t)b * Ss * Hh;
        float a = 0.0f;
        #pragma unroll 16
        for (int s = 0; s < Ss; s++)
            a = fmaf(swgt[s], encb[(size_t)s * Hh + t], a);
        g_scratch[OFF_RNN + (size_t)b * 3 * Hh + Hh + t] = a;
    }
}

// ============================================================
// LSTM pointwise: sum G_SPLIT gate partials + biases
// ============================================================
__global__ __launch_bounds__(256)
void lstm_kernel(const float* __restrict__ c0,
                 const float* __restrict__ b_ih,
                 const float* __restrict__ b_hh,
                 float* __restrict__ out)
{
    int b = blockIdx.x >> 1;
    int h = ((blockIdx.x & 1) << 8) + threadIdx.x;
    const float* gp = g_scratch + OFF_GATE + (size_t)b * (4*Hh);

    float ig = b_ih[h]        + b_hh[h];
    float fg = b_ih[Hh + h]   + b_hh[Hh + h];
    float gg = b_ih[2*Hh + h] + b_hh[2*Hh + h];
    float og = b_ih[3*Hh + h] + b_hh[3*Hh + h];
    #pragma unroll
    for (int z = 0; z < G_SPLIT; z++) {
        const float* pz = gp + (size_t)z * (Bb * 4 * Hh);
        ig += pz[h];
        fg += pz[Hh + h];
        gg += pz[2*Hh + h];
        og += pz[3*Hh + h];
    }

    float cn = sigmoidf_(fg) * c0[(size_t)b * Hh + h]
             + sigmoidf_(ig) * tanhf(gg);
    float hn = sigmoidf_(og) * tanhf(cn);

    out[(size_t)Bb * Vv + (size_t)b * Hh + h] = hn;
    out[(size_t)Bb * Vv + (size_t)Bb * Hh + (size_t)b * Hh + h] = cn;
}

// ============================================================
// kernel_launch
// ============================================================
extern "C" void kernel_launch(void* const* d_in, const int* in_sizes, int n_in,
                              void* d_out, int out_size)
{
    const int*   input_ids = (const int*)  d_in[0];
    const float* h0        = (const float*)d_in[1];
    const float* c0        = (const float*)d_in[2];
    const float* enc       = (const float*)d_in[3];
    const float* emb       = (const float*)d_in[4];
    const float* attn_W    = (const float*)d_in[5];
    const float* attn_b    = (const float*)d_in[6];
    const float* v         = (const float*)d_in[7];
    const float* W_ih      = (const float*)d_in[8];
    const float* W_hh      = (const float*)d_in[9];
    const float* b_ih      = (const float*)d_in[10];
    const float* b_hh      = (const float*)d_in[11];
    const float* fc_W      = (const float*)d_in[12];
    const float* fc_b      = (const float*)d_in[13];
    float* out = (float*)d_out;

    float* scratch = nullptr;
    cudaGetSymbolAddress((void**)&scratch, g_scratch);
    float* P_wh   = scratch + OFF_WH;
    float* rnn3   = scratch + OFF_RNN;
    float* P_g    = scratch + OFF_GATE;
    float* scores = scratch + OFF_SC;

    const int BIG = 1 << 30;

    // 1) P_wh[z] = h0 @ attn_W[:, :H]^T  (split-K 8; nk=2) + zero scores
    mma3h<false,false,true><<<dim3(Hh/128, 1, WH_SPLIT), 256, MMA3H_SMEM>>>(
        h0, Hh, attn_W, 2*Hh, attn_W, 2*Hh, BIG,
        P_wh, Hh, Bb*Hh, nullptr, Hh/WH_SPLIT,
        nullptr, nullptr, scores);

    // 2) fused We GEMM + score reduction (M=8192, N=512, K=512)
    mma3h<false,true,false><<<dim3(Hh/128, (Bb*Ss)/128, 1), 256, MMA3H_SMEM>>>(
        enc, Hh, attn_W + Hh, 2*Hh, attn_W + Hh, 2*Hh, BIG,
        nullptr, 0, 0, attn_b, Hh,
        P_wh, v, scores);

    // 3) embed + softmax + context
    attn_fused<<<Bb, 512>>>(input_ids, emb, h0, enc);

    // 4) P_g[z] = rnn3 @ [W_ih | W_hh]^T  [BN=64: 32 x 16 = 512 CTAs, nk=3]
    mma64<false><<<dim3((4*Hh)/64, 1, G_SPLIT), 256, MMA64_SMEM>>>(
        rnn3, 3*Hh, W_ih, 2*Hh, W_hh, Hh, 2*Hh,
        P_g, 4*Hh, Bb*4*Hh, nullptr, (3*Hh)/G_SPLIT);

    // 5) LSTM pointwise -> h_new, c_new
    lstm_kernel<<<2*Bb, 256>>>(c0, b_ih, b_hh, out);

    // 6) prediction = h_new @ fc_W^T + fc_b  [BN=64: 500 CTAs, nk=16]
    const float* h_new = out + (size_t)Bb * Vv;
    mma64<true><<<dim3(Vv/64, 1, 1), 256, MMA64_SMEM>>>(
        h_new, Hh, fc_W, Hh, fc_W, Hh, BIG,
        out, Vv, 0, fc_b, Hh);
}

// round 15
// speedup vs baseline: 1.1918x; 1.1918x over previous
#include <cuda_runtime.h>
#include <cuda_fp16.h>
#include <math.h>
#include <stdint.h>

#define Vv 32000
#define Hh 512
#define Bb 128
#define Ss 64

#define WH_SPLIT 8
#define G_SLICES 12          // 4 emb + 4 h0 + 4 ctx, Kslice=128 each

// ---- scratch ----
// P_wh[8][B*H] | rnn3[B*3H] | P_g[12][B*4H] | scores[B*S]
#define OFF_WH   0
#define OFF_RNN  (WH_SPLIT*Bb*Hh)
#define OFF_GATE (OFF_RNN + Bb*3*Hh)
#define OFF_SC   (OFF_GATE + G_SLICES*Bb*4*Hh)
#define SCRATCH_TOTAL (OFF_SC + Bb*Ss)
__device__ float g_scratch[SCRATCH_TOTAL];

__device__ __forceinline__ float sigmoidf_(float x) {
    return 1.0f / (1.0f + __expf(-x));
}
__device__ __forceinline__ float tanh_fast(float x) {
    float y; asm("tanh.approx.f32 %0, %1;" : "=f"(y) : "f"(x)); return y;
}
__device__ __forceinline__ uint32_t pack_h2(float lo, float hi) {
    uint32_t r;
    asm("cvt.rn.f16x2.f32 %0, %1, %2;" : "=r"(r) : "f"(hi), "f"(lo));
    return r;
}
__device__ __forceinline__ void mma_f16(float c[4],
    uint32_t a0, uint32_t a1, uint32_t a2, uint32_t a3,
    uint32_t b0, uint32_t b1)
{
    asm volatile(
        "mma.sync.aligned.m16n8k16.row.col.f32.f16.f16.f32 "
        "{%0,%1,%2,%3}, {%4,%5,%6,%7}, {%8,%9}, {%0,%1,%2,%3};"
        : "+f"(c[0]), "+f"(c[1]), "+f"(c[2]), "+f"(c[3])
        : "r"(a0), "r"(a1), "r"(a2), "r"(a3), "r"(b0), "r"(b1));
}
__device__ __forceinline__ void ldsm_x4(uint32_t& r0, uint32_t& r1,
                                        uint32_t& r2, uint32_t& r3,
                                        uint32_t saddr)
{
    asm volatile("ldmatrix.sync.aligned.m8n8.x4.shared.b16 {%0,%1,%2,%3}, [%4];"
                 : "=r"(r0), "=r"(r1), "=r"(r2), "=r"(r3) : "r"(saddr));
}

#define SSTH 40
#define HBUF (128*SSTH)
#define MMA3H_SMEM (4*HBUF*2)

// ============================================================
// BN=128 fp16 GEMM (R7/R12-proven skeleton) + score epilogue.
// kofs: absolute K offset (A col / Bcat col index use kofs +
// z*Kslice + k). zofs: output-slice offset (C += (zofs+z)*cslice).
// ============================================================
template<bool BIAS, bool SCORE, bool ZEROSC>
__global__ __launch_bounds__(256)
void mma3h(const float* __restrict__ A, int lda,
           const float* __restrict__ B0, int ldb0,
           const float* __restrict__ B1, int ldb1, int Kswitch,
           float* __restrict__ C, int ldc, int cslice,
           const float* __restrict__ bias, int Kslice,
           int kofs, int zofs,
           const float* __restrict__ Pwh,
           const float* __restrict__ vvec,
           float* __restrict__ scores)
{
    extern __shared__ __half shh[];

    const int m0 = blockIdx.y * 128;
    const int n0 = blockIdx.x * 128;
    const int kbase = kofs + blockIdx.z * Kslice;
    if (!SCORE) C += (size_t)(zofs + blockIdx.z) * cslice;

    const int t    = threadIdx.x;
    const int lane = t & 31;
    const int warp = t >> 5;
    const int wm = warp & 1;
    const int wn = warp >> 1;
    const int g  = lane >> 2;
    const int tg = lane & 3;

    if (ZEROSC) {
        int id = (blockIdx.z * gridDim.x + blockIdx.x) * 256 + t;
        scores[id] = 0.0f;
    }

    const uint32_t as_base = (uint32_t)__cvta_generic_to_shared(shh);
    const uint32_t bs_base = as_base + 2u * HBUF * 2u;
    const uint32_t a_loff = (uint32_t)(((lane & 15) * SSTH + ((lane >> 4) << 3)) * 2);
    const uint32_t b_loff = (uint32_t)((((lane & 7) + ((lane >> 4) << 3)) * SSTH
                                        + (((lane >> 3) & 1) << 3)) * 2);

    const int lrow = t >> 3;
    const int lcol = (t & 7) * 4;

    float4 abuf[4], bbuf[4];

    auto ldg_stage = [&](int kc) {
        #pragma unroll
        for (int i = 0; i < 4; i++) {
            int r = lrow + 32 * i;
            int kabs = kbase + kc + lcol;
            abuf[i] = *(const float4*)&A[(size_t)(m0 + r) * lda + kabs];
            const float* bp = (kabs < Kswitch)
                ? (B0 + (size_t)(n0 + r) * ldb0 + kabs)
                : (B1 + (size_t)(n0 + r) * ldb1 + (kabs - Kswitch));
            bbuf[i] = *(const float4*)bp;
        }
    };
    auto sts_stage = [&](int s) {
        __half* As = shh + (size_t)s * HBUF;
        __half* Bs = shh + 2 * HBUF + (size_t)s * HBUF;
        #pragma unroll
        for (int i = 0; i < 4; i++) {
            int r = lrow + 32 * i;
            uint2 ua = make_uint2(pack_h2(abuf[i].x, abuf[i].y),
                                  pack_h2(abuf[i].z, abuf[i].w));
            *(uint2*)&As[r * SSTH + lcol] = ua;
            uint2 ub = make_uint2(pack_h2(bbuf[i].x, bbuf[i].y),
                                  pack_h2(bbuf[i].z, bbuf[i].w));
            *(uint2*)&Bs[r * SSTH + lcol] = ub;
        }
    };

    float acc[4][4][4];
    #pragma unroll
    for (int mi = 0; mi < 4; mi++)
        #pragma unroll
        for (int ni = 0; ni < 4; ni++)
            #pragma unroll
            for (int k = 0; k < 4; k++) acc[mi][ni][k] = 0.0f;

    const int nk = Kslice >> 5;

    ldg_stage(0);
    sts_stage(0);
    if (nk > 1) ldg_stage(32);
    __syncthreads();

    for (int kt = 0; kt < nk; kt++) {
        const int cur = kt & 1;
        const uint32_t abufp = as_base + (uint32_t)cur * (HBUF * 2u);
        const uint32_t bbufp = bs_base + (uint32_t)cur * (HBUF * 2u);

        #pragma unroll
        for (int kk = 0; kk < 32; kk += 16) {
            uint32_t af[4][4], bf[4][2];
            #pragma unroll
            for (int mi = 0; mi < 4; mi++) {
                uint32_t addr = abufp
                    + (uint32_t)(((wm * 64 + mi * 16) * SSTH + kk) * 2) + a_loff;
                ldsm_x4(af[mi][0], af[mi][1], af[mi][2], af[mi][3], addr);
            }
            #pragma unroll
            for (int p = 0; p < 2; p++) {
                uint32_t addr = bbufp
                    + (uint32_t)(((wn * 32 + p * 16) * SSTH + kk) * 2) + b_loff;
                ldsm_x4(bf[2*p][0], bf[2*p][1], bf[2*p+1][0], bf[2*p+1][1], addr);
            }
            #pragma unroll
            for (int mi = 0; mi < 4; mi++)
                #pragma unroll
                for (int ni = 0; ni < 4; ni++)
                    mma_f16(acc[mi][ni],
                            af[mi][0], af[mi][1], af[mi][2], af[mi][3],
                            bf[ni][0], bf[ni][1]);
        }

        if (kt + 1 < nk) {
            sts_stage(cur ^ 1);
            __syncthreads();
            if (kt + 2 < nk) ldg_stage((kt + 2) << 5);
        }
    }

    if (SCORE) {
        float* sW = (float*)shh;           // [2][128]
        float* sv = sW + 256;              // [128]
        __syncthreads();
        {
            const int b0 = m0 >> 6;
            const int bi = t >> 7;
            const int nn = t & 127;
            float w = bias[n0 + nn];       // attn_b
            #pragma unroll
            for (int z = 0; z < WH_SPLIT; z++)
                w += Pwh[(size_t)z * Bb * Hh + (size_t)(b0 + bi) * Hh + n0 + nn];
            sW[bi * 128 + nn] = w;
            if (t < 128) sv[t] = vvec[n0 + t];
        }
        __syncthreads();

        #pragma unroll
        for (int mi = 0; mi < 4; mi++) {
            #pragma unroll
            for (int ci = 0; ci < 2; ci++) {
                int r  = wm * 64 + mi * 16 + g + ci * 8;
                int rb = r >> 6;
                float part = 0.0f;
                #pragma unroll
                for (int ni = 0; ni < 4; ni++) {
                    int nl = wn * 32 + ni * 8 + tg * 2;
                    part += sv[nl]     * tanh_fast(acc[mi][ni][ci*2+0] + sW[rb*128 + nl]);
                    part += sv[nl + 1] * tanh_fast(acc[mi][ni][ci*2+1] + sW[rb*128 + nl + 1]);
                }
                part += __shfl_xor_sync(0xFFFFFFFFu, part, 1);
                part += __shfl_xor_sync(0xFFFFFFFFu, part, 2);
                if (tg == 0)
                    atomicAdd(&scores[m0 + r], part);
            }
        }
        return;
    }

    #pragma unroll
    for (int mi = 0; mi < 4; mi++) {
        #pragma unroll
        for (int ci = 0; ci < 2; ci++) {
            int m = m0 + wm * 64 + mi * 16 + g + ci * 8;
            #pragma unroll
            for (int ni = 0; ni < 4; ni++) {
                int n = n0 + wn * 32 + ni * 8 + tg * 2;
                float2 vo;
                vo.x = acc[mi][ni][ci * 2 + 0];
                vo.y = acc[mi][ni][ci * 2 + 1];
                if (BIAS) { vo.x += bias[n]; vo.y += bias[n + 1]; }
                *(float2*)&C[(size_t)m * ldc + n] = vo;
            }
        }
    }
}

// ============================================================
// embed: rnn3[b][0:H] = emb[ids[b]]; rnn3[b][2H:3H] = h0[b]
// ============================================================
__global__ __launch_bounds__(512)
void embed_kernel(const int* __restrict__ input_ids,
                  const float* __restrict__ emb,
                  const float* __restrict__ h0)
{
    const int b = blockIdx.x;
    const int t = threadIdx.x;
    int idx = input_ids[b];
    float* rnn3 = g_scratch + OFF_RNN + (size_t)b * (3*Hh);
    rnn3[t]        = emb[(size_t)idx * Hh + t];
    rnn3[2*Hh + t] = h0[(size_t)b * Hh + t];
}

// ============================================================
// ctx: softmax(scores) + context -> rnn3[:, H:2H]
// ============================================================
__global__ __launch_bounds__(512)
void ctx_kernel(const float* __restrict__ enc)
{
    const int b = blockIdx.x;
    const int t = threadIdx.x;
    const int lane = t & 31, warp = t >> 5;

    __shared__ float swgt[Ss];

    if (warp == 0) {
        float x0 = g_scratch[OFF_SC + (size_t)b * Ss + lane];
        float x1 = g_scratch[OFF_SC + (size_t)b * Ss + lane + 32];
        float mx = fmaxf(x0, x1);
        #pragma unroll
        for (int off = 16; off > 0; off >>= 1)
            mx = fmaxf(mx, __shfl_xor_sync(0xFFFFFFFFu, mx, off));
        float e0 = expf(x0 - mx), e1 = expf(x1 - mx);
        float sum = e0 + e1;
        #pragma unroll
        for (int off = 16; off > 0; off >>= 1)
            sum += __shfl_xor_sync(0xFFFFFFFFu, sum, off);
        float inv = 1.0f / sum;
        swgt[lane]      = e0 * inv;
        swgt[lane + 32] = e1 * inv;
    }
    __syncthreads();

    const float* encb = enc + (size_t)b * Ss * Hh;
    float a = 0.0f;
    #pragma unroll 16
    for (int s = 0; s < Ss; s++)
        a = fmaf(swgt[s], encb[(size_t)s * Hh + t], a);
    g_scratch[OFF_RNN + (size_t)b * 3 * Hh + Hh + t] = a;
}

// ============================================================
// LSTM pointwise: sum G_SLICES gate partials + biases
// ============================================================
__global__ __launch_bounds__(256)
void lstm_kernel(const float* __restrict__ c0,
                 const float* __restrict__ b_ih,
                 const float* __restrict__ b_hh,
                 float* __restrict__ out)
{
    int b = blockIdx.x >> 1;
    int h = ((blockIdx.x & 1) << 8) + threadIdx.x;
    const float* gp = g_scratch + OFF_GATE + (size_t)b * (4*Hh);

    float ig = b_ih[h]        + b_hh[h];
    float fg = b_ih[Hh + h]   + b_hh[Hh + h];
    float gg = b_ih[2*Hh + h] + b_hh[2*Hh + h];
    float og = b_ih[3*Hh + h] + b_hh[3*Hh + h];
    #pragma unroll
    for (int z = 0; z < G_SLICES; z++) {
        const float* pz = gp + (size_t)z * (Bb * 4 * Hh);
        ig += pz[h];
        fg += pz[Hh + h];
        gg += pz[2*Hh + h];
        og += pz[3*Hh + h];
    }

    float cn = sigmoidf_(fg) * c0[(size_t)b * Hh + h]
             + sigmoidf_(ig) * tanhf(gg);
    float hn = sigmoidf_(og) * tanhf(cn);

    out[(size_t)Bb * Vv + (size_t)b * Hh + h] = hn;
    out[(size_t)Bb * Vv + (size_t)Bb * Hh + (size_t)b * Hh + h] = cn;
}

// ============================================================
// kernel_launch — gates emb/h0 slices overlap the attention
// chain on a side stream (fork after embed, join before lstm).
// ============================================================
extern "C" void kernel_launch(void* const* d_in, const int* in_sizes, int n_in,
                              void* d_out, int out_size)
{
    const int*   input_ids = (const int*)  d_in[0];
    const float* h0        = (const float*)d_in[1];
    const float* c0        = (const float*)d_in[2];
    const float* enc       = (const float*)d_in[3];
    const float* emb       = (const float*)d_in[4];
    const float* attn_W    = (const float*)d_in[5];
    const float* attn_b    = (const float*)d_in[6];
    const float* v         = (const float*)d_in[7];
    const float* W_ih      = (const float*)d_in[8];
    const float* W_hh      = (const float*)d_in[9];
    const float* b_ih      = (const float*)d_in[10];
    const float* b_hh      = (const float*)d_in[11];
    const float* fc_W      = (const float*)d_in[12];
    const float* fc_b      = (const float*)d_in[13];
    float* out = (float*)d_out;

    float* scratch = nullptr;
    cudaGetSymbolAddress((void**)&scratch, g_scratch);
    float* P_wh   = scratch + OFF_WH;
    float* rnn3   = scratch + OFF_RNN;
    float* P_g    = scratch + OFF_GATE;
    float* scores = scratch + OFF_SC;

    const int BIG = 1 << 30;
    const int GC  = Bb * 4 * Hh;   // gate partial slice size

    cudaStream_t side;
    cudaEvent_t e_fork, e_join;
    cudaStreamCreateWithFlags(&side, cudaStreamNonBlocking);
    cudaEventCreateWithFlags(&e_fork, cudaEventDisableTiming);
    cudaEventCreateWithFlags(&e_join, cudaEventDisableTiming);

    // 0) embed + h0 copy -> rnn3 (needed by side-stream gates)
    embed_kernel<<<Bb, 512>>>(input_ids, emb, h0);
    cudaEventRecord(e_fork, 0);
    cudaStreamWaitEvent(side, e_fork, 0);

    // ---- side stream: gates slices that don't need context ----
    // emb part: K in [0,512), W_ih cols [0,512) -> output slices 0-3
    mma3h<false,false,false><<<dim3((4*Hh)/128, 1, 4), 256, MMA3H_SMEM, side>>>(
        rnn3, 3*Hh, W_ih, 2*Hh, W_ih, 2*Hh, BIG,
        P_g, 4*Hh, GC, nullptr, 128, /*kofs=*/0, /*zofs=*/0,
        nullptr, nullptr, nullptr);
    // h0 part: K in [1024,1536), W_hh cols [0,512) -> output slices 4-7
    mma3h<false,false,false><<<dim3((4*Hh)/128, 1, 4), 256, MMA3H_SMEM, side>>>(
        rnn3, 3*Hh, W_ih, 2*Hh, W_hh, Hh, /*Kswitch=*/2*Hh,
        P_g, 4*Hh, GC, nullptr, 128, /*kofs=*/2*Hh, /*zofs=*/4,
        nullptr, nullptr, nullptr);
    cudaEventRecord(e_join, side);

    // ---- main stream: attention chain ----
    // 1) P_wh[z] = h0 @ attn_W[:, :H]^T (split-K 8) + zero scores
    mma3h<false,false,true><<<dim3(Hh/128, 1, WH_SPLIT), 256, MMA3H_SMEM>>>(
        h0, Hh, attn_W, 2*Hh, attn_W, 2*Hh, BIG,
        P_wh, Hh, Bb*Hh, nullptr, Hh/WH_SPLIT, 0, 0,
        nullptr, nullptr, scores);

    // 2) fused We GEMM + score reduction
    mma3h<false,true,false><<<dim3(Hh/128, (Bb*Ss)/128, 1), 256, MMA3H_SMEM>>>(
        enc, Hh, attn_W + Hh, 2*Hh, attn_W + Hh, 2*Hh, BIG,
        nullptr, 0, 0, attn_b, Hh, 0, 0,
        P_wh, v, scores);

    // 3) softmax + context -> rnn3[:, H:2H]
    ctx_kernel<<<Bb, 512>>>(enc);

    // 4) gates ctx part: K in [512,1024), W_ih cols [512,1024)
    //    -> output slices 8-11
    mma3h<false,false,false><<<dim3((4*Hh)/128, 1, 4), 256, MMA3H_SMEM>>>(
        rnn3, 3*Hh, W_ih, 2*Hh, W_ih, 2*Hh, BIG,
        P_g, 4*Hh, GC, nullptr, 128, /*kofs=*/Hh, /*zofs=*/8,
        nullptr, nullptr, nullptr);

    // join side-stream gates before lstm
    cudaStreamWaitEvent(0, e_join, 0);

    // 5) LSTM pointwise -> h_new, c_new
    lstm_kernel<<<2*Bb, 256>>>(c0, b_ih, b_hh, out);

    // 6) prediction = h_new @ fc_W^T + fc_b
    const float* h_new = out + (size_t)Bb * Vv;
    mma3h<true,false,false><<<dim3(Vv/128, 1, 1), 256, MMA3H_SMEM>>>(
        h_new, Hh, fc_W, Hh, fc_W, Hh, BIG,
        out, Vv, 0, fc_b, Hh, 0, 0,
        nullptr, nullptr, nullptr);

    cudaStreamDestroy(side);
    cudaEventDestroy(e_fork);
    cudaEventDestroy(e_join);
}